// round 15
// baseline (speedup 1.0000x reference)
#include <cuda_runtime.h>
#include <cuda_fp16.h>
#include <math.h>
#include <stdint.h>

#define BDIM 4
#define SEQ 1024
#define DMODEL 1024
#define NH 16
#define DH 64
#define SPAN 256
#define TWOSPAN 512
#define NBATCH (BDIM*NH)   /* 64 */
#define NEGF (-3.402823466e38f)
#define QKOFF ((size_t)NBATCH * SEQ * DH)
#define PKOFF ((size_t)NH * TWOSPAN * DH)
#define BIASOFF ((size_t)NBATCH * SEQ * TWOSPAN)
#define LOG2E 1.4426950408889634f

// ---------------- scratch (device globals; no allocation allowed) ----------
__device__ __half    g_hh   [(size_t)BDIM * SEQ * DMODEL];     // hidden fp16
__device__ __half    g_wqkv [(size_t)3 * DMODEL * DMODEL];     // packed Wq|Wk|Wv fp16
__device__ float     g_bqkv [3 * DMODEL];                       // packed bq|bk|bv
__device__ __half    g_wo   [(size_t)DMODEL * DMODEL];
__device__ __half    g_relh [(size_t)TWOSPAN * DMODEL];
__device__ __half    g_qkh  [(size_t)2 * NBATCH * SEQ * DH];   // qh | kh
__device__ __half    g_vt   [(size_t)NBATCH * DH * SEQ];       // [z][d][s]
__device__ __half    g_pkq  [(size_t)2 * NH * TWOSPAN * DH];   // pk | pq
__device__ __half    g_bias2[(size_t)2 * NBATCH * SEQ * TWOSPAN]; // c2p | p2cT (log2e-scaled)
__device__ __half    g_ctx  [(size_t)BDIM * SEQ * DMODEL];
__device__ uint32_t  g_mbits[(size_t)BDIM * SEQ * 32];          // packed mask bits
__device__ int       g_lut  [2047];

// ================= small helpers ============================================
#define MMA_F16(d, a, b) \
    asm volatile("mma.sync.aligned.m16n8k16.row.col.f32.f16.f16.f32 " \
        "{%0,%1,%2,%3}, {%4,%5,%6,%7}, {%8,%9}, {%0,%1,%2,%3};" \
        : "+f"((d)[0]), "+f"((d)[1]), "+f"((d)[2]), "+f"((d)[3]) \
        : "r"((a)[0]), "r"((a)[1]), "r"((a)[2]), "r"((a)[3]), \
          "r"((b)[0]), "r"((b)[1]))

#define LDSM_X4(r0, r1, r2, r3, addr) \
    asm volatile("ldmatrix.sync.aligned.m8n8.x4.shared.b16 {%0,%1,%2,%3}, [%4];" \
        : "=r"(r0), "=r"(r1), "=r"(r2), "=r"(r3) : "r"(addr))

__device__ __forceinline__ uint32_t pack_h2(float lo, float hi) {
    uint32_t u;
    asm("cvt.rn.f16x2.f32 %0, %1, %2;" : "=r"(u) : "f"(hi), "f"(lo));
    return u;
}
__device__ __forceinline__ float ex2f(float x) {
    float r;
    asm("ex2.approx.f32 %0, %1;" : "=f"(r) : "f"(x));
    return r;
}
__device__ __forceinline__ void cp16(uint32_t dst, const void* src) {
    asm volatile("cp.async.cg.shared.global [%0], [%1], 16;" :: "r"(dst), "l"(src));
}
#define CP_COMMIT() asm volatile("cp.async.commit_group;" ::: "memory")
#define CP_WAIT(n)  asm volatile("cp.async.wait_group %0;" :: "n"(n) : "memory")

// ================= prep kernels =============================================
__global__ void cvt_k(const float* __restrict__ s, __half* __restrict__ d, int n) {
    int i = (blockIdx.x * blockDim.x + threadIdx.x) << 2;
    if (i >= n) return;
    float4 v = *(const float4*)(s + i);
    uint2 o = make_uint2(pack_h2(v.x, v.y), pack_h2(v.z, v.w));
    *(uint2*)((char*)d + (size_t)i * 2) = o;
}
__global__ void bias3_k(const float* __restrict__ a, const float* __restrict__ b,
                        const float* __restrict__ c, float* __restrict__ d) {
    int t = blockIdx.x * blockDim.x + threadIdx.x;
    if (t < DMODEL) { d[t] = a[t]; d[DMODEL + t] = b[t]; d[2 * DMODEL + t] = c[t]; }
}
__global__ void maskpack_k(const int* __restrict__ m, uint32_t* __restrict__ bm) {
    int idx = blockIdx.x * blockDim.x + threadIdx.x;
    const int4* src = (const int4*)(m + (size_t)idx * 32);
    uint32_t v = 0;
    #pragma unroll
    for (int g = 0; g < 8; g++) {
        int4 x = src[g];
        v |= (x.x ? 1u : 0u) << (4 * g);
        v |= (x.y ? 1u : 0u) << (4 * g + 1);
        v |= (x.z ? 1u : 0u) << (4 * g + 2);
        v |= (x.w ? 1u : 0u) << (4 * g + 3);
    }
    bm[idx] = v;
}
__device__ __forceinline__ int rel_bucket(int rel) {
    float abs_pos = (rel < 128 && rel > -128) ? 127.0f : fabsf((float)rel);
    if (abs_pos <= 128.0f) return rel;
    float sgn = (rel > 0) ? 1.0f : -1.0f;
    float log_pos = ceilf(logf(abs_pos * (1.0f/128.0f)) / logf(511.0f/128.0f) * 127.0f) + 128.0f;
    return (int)(log_pos * sgn);
}
__global__ void lut_k() {
    int t = blockIdx.x * blockDim.x + threadIdx.x;
    if (t >= 2047) return;
    int b = rel_bucket(t - 1023);
    g_lut[t] = min(max(b + SPAN, 0), TWOSPAN - 1);
}

// ================= unified fp16 mma.sync GEMM (C = A @ B^T + epilogues) =====
#define EPI_POS     2
#define EPI_SCALE   3
#define EPI_OUT     6
#define EPI_QKV     7

template<int EPI, int CH>
__global__ void __launch_bounds__(256, 2)
tc_gemm_h(const __half* __restrict__ A, const __half* __restrict__ Bm,
          const float* __restrict__ bias, const float* __restrict__ ex1,
          float* __restrict__ C, __half* __restrict__ Ch,
          int Ka)
{
    constexpr int NS = 3;
    constexpr int TB = 128 * 128;

    extern __shared__ char smc[];
    const uint32_t smemU = (uint32_t)__cvta_generic_to_shared(smc);

    const int tid  = threadIdx.x;
    const int lane = tid & 31, wid = tid >> 5;
    const int wr = wid & 1, wc = wid >> 1;
    const int rq = lane >> 2, cc = lane & 3;
    const int z  = blockIdx.z;

    int m0, n0;
    size_t cbase = 0;
    int ldC = 0;
    int half = 0, zz = 0;
    if (EPI == EPI_SCALE) {
        half = z >> 6; zz = z & 63;
        int ti = blockIdx.x;
        int mt = half ? (ti & 3) : (ti >> 2);
        int nt = half ? (ti >> 2) : (ti & 3);
        m0 = mt * 128; n0 = nt * 128;
        const __half* qk  = A;     // g_qkh
        const __half* pkq = Bm;    // g_pkq
        if (half) {
            A  = pkq + PKOFF + (size_t)(zz % NH) * TWOSPAN * DH;
            Bm = qk + QKOFF + (size_t)zz * SEQ * DH;
        } else {
            A  = qk + (size_t)zz * SEQ * DH;
            Bm = pkq + (size_t)(zz % NH) * TWOSPAN * DH;
        }
        cbase = ((size_t)half * NBATCH + zz) * ((size_t)SEQ * TWOSPAN);
        ldC = half ? SEQ : TWOSPAN;
        A  += (size_t)m0 * Ka;
        Bm += (size_t)n0 * Ka;
    } else {
        m0 = blockIdx.y * 128;
        n0 = blockIdx.x * 128;
        if (EPI == EPI_QKV) {
            Bm += (size_t)z * DMODEL * DMODEL;
        } else if (EPI == EPI_POS) {
            Bm += (size_t)(1 - z) * DMODEL * DMODEL;   // z=0->Wk, z=1->Wq
        }
        A  += (size_t)m0 * Ka;
        Bm += (size_t)n0 * Ka;
    }

    float acc[4][4][4];
    #pragma unroll
    for (int a = 0; a < 4; a++)
        #pragma unroll
        for (int b = 0; b < 4; b++)
            #pragma unroll
            for (int c = 0; c < 4; c++) acc[a][b][c] = 0.0f;

    const int crow = tid >> 3;
    const int cg   = tid & 7;

    auto issue = [&](int chunk) {
        const int s  = chunk % NS;
        const int k0 = chunk * 64;
        #pragma unroll
        for (int j = 0; j < 4; j++) {
            int row = j * 32 + crow;
            cp16(smemU + (uint32_t)(s * TB + row * 128 + ((cg ^ (row & 7)) << 4)),
                 A + (size_t)row * Ka + k0 + cg * 8);
        }
        #pragma unroll
        for (int j = 0; j < 4; j++) {
            int row = j * 32 + crow;
            cp16(smemU + (uint32_t)(NS * TB + s * TB + row * 128 + ((cg ^ (row & 7)) << 4)),
                 Bm + (size_t)row * Ka + k0 + cg * 8);
        }
    };

    #pragma unroll
    for (int c = 0; c < NS - 1; c++) {
        if (c < CH) issue(c);
        CP_COMMIT();
    }

    // LDSM lane geometry
    const int l7 = lane & 7;
    const uint32_t aRow = (uint32_t)(wr * 64 + (lane & 15)) * 128;   // + mi*2048
    const int gA = lane >> 4;                                        // A group half
    const uint32_t bRow = (uint32_t)(wc * 32 + l7 + ((lane >> 4) << 3)) * 128;  // + pair*2048
    const int gB = (lane >> 3) & 1;                                  // B group half

    #pragma unroll 1
    for (int i = 0; i < CH; i++) {
        CP_WAIT(NS - 2);
        __syncthreads();
        if (i + NS - 1 < CH) issue(i + NS - 1);
        CP_COMMIT();

        const uint32_t asB = smemU + (uint32_t)((i % NS) * TB);
        const uint32_t bsB = smemU + (uint32_t)(NS * TB + (i % NS) * TB);
        #pragma unroll
        for (int kc = 0; kc < 4; kc++) {
            const uint32_t swA = (uint32_t)(((2 * kc + gA) ^ l7) << 4);
            const uint32_t swB = (uint32_t)(((2 * kc + gB) ^ l7) << 4);
            uint32_t af[4][4];
            #pragma unroll
            for (int mi = 0; mi < 4; mi++)
                LDSM_X4(af[mi][0], af[mi][1], af[mi][2], af[mi][3],
                        asB + aRow + (uint32_t)(mi * 2048) + swA);
            uint32_t bf[4][2];
            LDSM_X4(bf[0][0], bf[0][1], bf[1][0], bf[1][1], bsB + bRow + swB);
            LDSM_X4(bf[2][0], bf[2][1], bf[3][0], bf[3][1], bsB + bRow + 2048u + swB);
            #pragma unroll
            for (int mi = 0; mi < 4; mi++)
                #pragma unroll
                for (int ni = 0; ni < 4; ni++)
                    MMA_F16(acc[mi][ni], af[mi], bf[ni]);
        }
    }
    CP_WAIT(0);
    __syncthreads();

    // ---------------- epilogue: frags -> smem stage -> global ----------------
    float* stage = (float*)smc;
    const int boff = (EPI == EPI_QKV) ? z * DMODEL : (EPI == EPI_POS ? (1 - z) * DMODEL : 0);
    const bool transT = (EPI == EPI_QKV && z == 2);
    const float alpha = 0.072168783648703216f * LOG2E;   // 1/sqrt(192) * log2e

    #pragma unroll 1
    for (int cb = 0; cb < 4; cb++) {
        const int n0c = n0 + cb * 32;
        #pragma unroll
        for (int mi = 0; mi < 4; mi++)
            #pragma unroll
            for (int ni = 0; ni < 4; ni++) {
                int gc = wc * 32 + ni * 8 + 2 * cc;
                if ((gc >> 5) == cb) {
                    int sc2 = gc & 31;
                    int r0 = wr * 64 + mi * 16 + rq;
                    stage[r0 * 33 + sc2]           = acc[mi][ni][0];
                    stage[r0 * 33 + sc2 + 1]       = acc[mi][ni][1];
                    stage[(r0 + 8) * 33 + sc2]     = acc[mi][ni][2];
                    stage[(r0 + 8) * 33 + sc2 + 1] = acc[mi][ni][3];
                }
            }
        __syncthreads();

        if (transT) {
            __half* Vp = (__half*)C;
            #pragma unroll 1
            for (int j = 0; j < 16; j++) {
                int e = j * 256 + tid;
                int row = e & 127, c = e >> 7;
                int m = m0 + row, n = n0c + c;
                float val = stage[row * 33 + c] + bias[boff + n];
                int b = m >> 10, sq = m & 1023;
                int zidx = b * NH + (n >> 6), dd = n & 63;
                Vp[((size_t)zidx * DH + dd) * SEQ + sq] = __float2half(val);
            }
        } else {
            #pragma unroll 1
            for (int j = 0; j < 16; j++) {
                int e = j * 256 + tid;
                int row = e >> 5, c = e & 31;
                int m = m0 + row, n = n0c + c;
                float val = stage[row * 33 + c];
                if (EPI == EPI_QKV) {
                    val += bias[boff + n];
                    int b = m >> 10, sq = m & 1023, h = n >> 6, dd = n & 63;
                    size_t idx = (((size_t)(b * NH + h)) * SEQ + sq) * DH + dd;
                    Ch[(size_t)z * QKOFF + idx] = __float2half(val);
                } else if (EPI == EPI_POS) {
                    val += bias[boff + n];
                    int h = n >> 6, dd = n & 63;
                    Ch[(size_t)z * PKOFF + ((size_t)h * TWOSPAN + m) * DH + dd] = __float2half(val);
                } else if (EPI == EPI_SCALE) {
                    Ch[cbase + (size_t)m * ldC + n] = __float2half(val * alpha);
                } else { // EPI_OUT
                    val += bias[n] + ex1[(size_t)m * DMODEL + n];
                    C[(size_t)m * DMODEL + n] = val;
                }
            }
        }
        __syncthreads();
    }
}

// ================= flash attention (fp16 MMA, LDSM feeds, exp2 softmax) =====
// grid (8 q-tiles, 64 z), 256 threads = 8 warps; warp w owns q rows 16w..16w+15.
// smem bytes: Q 16K | K 3x8K | V 3x8K | lut 8K => 72KB, 2 CTA/SM
__global__ void __launch_bounds__(256, 2)
flash_k(const __half* __restrict__ Qg, const __half* __restrict__ Kg,
        const __half* __restrict__ Vg, const __half* __restrict__ c2p,
        const __half* __restrict__ p2cT, const uint32_t* __restrict__ mbits,
        __half* __restrict__ ctx, float alpha)
{
    constexpr int QSB = 0, KSB = 16384, VSB = 40960, LUTB = 65536;
    extern __shared__ float fsm[];
    char* smc = (char*)fsm;
    int* lut_s = (int*)(smc + LUTB);
    const uint32_t smemU = (uint32_t)__cvta_generic_to_shared(fsm);

    const int tid = threadIdx.x, lane = tid & 31, w = tid >> 5;
    const int rq = lane >> 2, cc = lane & 3;
    const int z = blockIdx.y, m0 = blockIdx.x * 128;
    const int b = z >> 4;

    const __half* Qz = Qg + (size_t)z * SEQ * DH;
    const __half* Kz = Kg + (size_t)z * SEQ * DH;
    const __half* Vz = Vg + (size_t)z * DH * SEQ;
    const __half* c2pz = c2p + (size_t)z * SEQ * TWOSPAN;
    const __half* p2cz = p2cT + (size_t)z * TWOSPAN * SEQ;

    for (int t = tid; t < 2047; t += 256) lut_s[t] = g_lut[t];

    #pragma unroll
    for (int it = 0; it < 4; it++) {
        int idx = it * 256 + tid;
        int row = idx >> 3, g = idx & 7;
        cp16(smemU + (uint32_t)(QSB + row * 128 + ((g ^ (row & 7)) << 4)),
             Qz + (size_t)(m0 + row) * DH + g * 8);
    }
    auto issueKV = [&](int t) {
        int s = t % 3, n0 = t * 64;
        #pragma unroll
        for (int it = 0; it < 2; it++) {
            int idx = it * 256 + tid;
            int row = idx >> 3, g = idx & 7;
            cp16(smemU + (uint32_t)(KSB + s * 8192 + row * 128 + ((g ^ (row & 7)) << 4)),
                 Kz + (size_t)(n0 + row) * DH + g * 8);
        }
        #pragma unroll
        for (int it = 0; it < 2; it++) {
            int idx = it * 256 + tid;
            int row = idx >> 3, g = idx & 7;
            cp16(smemU + (uint32_t)(VSB + s * 8192 + row * 128 + ((g ^ (row & 7)) << 4)),
                 Vz + (size_t)row * SEQ + n0 + g * 8);
        }
    };
    issueKV(0);
    CP_COMMIT();
    issueKV(1);
    CP_COMMIT();

    float oacc[8][4];
    #pragma unroll
    for (int f = 0; f < 8; f++)
        #pragma unroll
        for (int e = 0; e < 4; e++) oacc[f][e] = 0.0f;
    float mrow[2] = {NEGF, NEGF};
    float lrow[2] = {0.0f, 0.0f};

    const int iA = m0 + 16 * w + rq, iB = iA + 8;
    const __half* c2pA = c2pz + (size_t)iA * TWOSPAN;
    const __half* c2pB = c2pz + (size_t)iB * TWOSPAN;
    const uint32_t* bmA = mbits + ((size_t)b * SEQ + iA) * 32;
    const uint32_t* bmB = mbits + ((size_t)b * SEQ + iB) * 32;

    // LDSM lane geometry
    const int l7 = lane & 7;
    const uint32_t qRow = (uint32_t)(16 * w + (lane & 15)) * 128;
    const int gA = lane >> 4;
    const uint32_t bRow = (uint32_t)(l7 + ((lane >> 4) << 3)) * 128;   // + pair*2048
    const int gB = (lane >> 3) & 1;

    #pragma unroll 1
    for (int t = 0; t < 16; t++) {
        const int s = t % 3, n0 = t * 64;
        CP_WAIT(1);
        __syncthreads();
        if (t + 2 < 16) issueKV(t + 2);
        CP_COMMIT();

        // ---- S = Q @ K^T (fp16, LDSM feeds) ----
        float sacc[8][4];
        #pragma unroll
        for (int f = 0; f < 8; f++)
            #pragma unroll
            for (int e = 0; e < 4; e++) sacc[f][e] = 0.0f;
        const uint32_t kBase = smemU + (uint32_t)(KSB + s * 8192);
        #pragma unroll
        for (int kc = 0; kc < 4; kc++) {
            const uint32_t swA = (uint32_t)(((2 * kc + gA) ^ l7) << 4);
            const uint32_t swB = (uint32_t)(((2 * kc + gB) ^ l7) << 4);
            uint32_t a[4];
            LDSM_X4(a[0], a[1], a[2], a[3], smemU + QSB + qRow + swA);
            #pragma unroll
            for (int p = 0; p < 4; p++) {
                uint32_t k0r, k1r, k2r, k3r;
                LDSM_X4(k0r, k1r, k2r, k3r, kBase + bRow + (uint32_t)(p * 2048) + swB);
                uint32_t bf0[2] = {k0r, k1r}, bf1[2] = {k2r, k3r};
                MMA_F16(sacc[2 * p],     a, bf0);
                MMA_F16(sacc[2 * p + 1], a, bf1);
            }
        }

        // ---- mask bits for this 64-wide tile ----
        uint2 wA2 = *(const uint2*)&bmA[n0 >> 5];
        uint2 wB2 = *(const uint2*)&bmB[n0 >> 5];
        uint64_t mwA = (uint64_t)wA2.x | ((uint64_t)wA2.y << 32);
        uint64_t mwB = (uint64_t)wB2.x | ((uint64_t)wB2.y << 32);

        // ---- scale + c2p + p2c + mask, row max (log2-domain) ----
        float mx0 = NEGF, mx1 = NEGF;
        #pragma unroll
        for (int f = 0; f < 8; f++) {
            int jl = 8 * f + 2 * cc;
            int j0 = n0 + jl;
            bool ma0 = (mwA >> jl) & 1, ma1 = (mwA >> (jl + 1)) & 1;
            bool mb0 = (mwB >> jl) & 1, mb1 = (mwB >> (jl + 1)) & 1;
            float v0 = ma0 ? sacc[f][0] * alpha + __half2float(c2pA[lut_s[iA - j0 + 1023]])
                             + __half2float(p2cz[(size_t)lut_s[j0 - iA + 1023] * SEQ + j0]) : NEGF;
            float v1 = ma1 ? sacc[f][1] * alpha + __half2float(c2pA[lut_s[iA - j0 + 1022]])
                             + __half2float(p2cz[(size_t)lut_s[j0 + 1 - iA + 1023] * SEQ + j0 + 1]) : NEGF;
            float v2 = mb0 ? sacc[f][2] * alpha + __half2float(c2pB[lut_s[iB - j0 + 1023]])
                             + __half2float(p2cz[(size_t)lut_s[j0 - iB + 1023] * SEQ + j0]) : NEGF;
            float v3 = mb1 ? sacc[f][3] * alpha + __half2float(c2pB[lut_s[iB - j0 + 1022]])
                             + __half2float(p2cz[(size_t)lut_s[j0 + 1 - iB + 1023] * SEQ + j0 + 1]) : NEGF;
            sacc[f][0] = v0; sacc[f][1] = v1; sacc[f][2] = v2; sacc[f][3] = v3;
            mx0 = fmaxf(mx0, fmaxf(v0, v1));
            mx1 = fmaxf(mx1, fmaxf(v2, v3));
        }
        mx0 = fmaxf(mx0, __shfl_xor_sync(0xffffffffu, mx0, 1));
        mx0 = fmaxf(mx0, __shfl_xor_sync(0xffffffffu, mx0, 2));
        mx1 = fmaxf(mx1, __shfl_xor_sync(0xffffffffu, mx1, 1));
        mx1 = fmaxf(mx1, __shfl_xor_sync(0xffffffffu, mx1, 2));
        float mn0 = fmaxf(mrow[0], mx0), mn1 = fmaxf(mrow[1], mx1);
        float sc0 = ex2f(mrow[0] - mn0), sc1 = ex2f(mrow[1] - mn1);
        mrow[0] = mn0; mrow[1] = mn1;

        // ---- exp2, pack P to fp16 A-fragments in-register ----
        float rs0 = 0.0f, rs1 = 0.0f;
        uint32_t ph[8][2];
        #pragma unroll
        for (int f = 0; f < 8; f++) {
            float e0 = ex2f(sacc[f][0] - mn0);
            float e1 = ex2f(sacc[f][1] - mn0);
            float e2 = ex2f(sacc[f][2] - mn1);
            float e3 = ex2f(sacc[f][3] - mn1);
            rs0 += e0 + e1; rs1 += e2 + e3;
            float p0 = (sacc[f][0] == NEGF) ? 0.0f : e0;
            float p1 = (sacc[f][1] == NEGF) ? 0.0f : e1;
            float p2 = (sacc[f][2] == NEGF) ? 0.0f : e2;
            float p3 = (sacc[f][3] == NEGF) ? 0.0f : e3;
            ph[f][0] = pack_h2(p0, p1);
            ph[f][1] = pack_h2(p2, p3);
        }
        rs0 += __shfl_xor_sync(0xffffffffu, rs0, 1);
        rs0 += __shfl_xor_sync(0xffffffffu, rs0, 2);
        rs1 += __shfl_xor_sync(0xffffffffu, rs1, 1);
        rs1 += __shfl_xor_sync(0xffffffffu, rs1, 2);
        lrow[0] = lrow[0] * sc0 + rs0;
        lrow[1] = lrow[1] * sc1 + rs1;
        #pragma unroll
        for (int f = 0; f < 8; f++) {
            oacc[f][0] *= sc0; oacc[f][1] *= sc0;
            oacc[f][2] *= sc1; oacc[f][3] *= sc1;
        }

        // ---- O += P @ V (fp16, LDSM V feeds) ----
        const uint32_t vBase = smemU + (uint32_t)(VSB + s * 8192);
        #pragma unroll
        for (int ks2 = 0; ks2 < 4; ks2++) {
            uint32_t a[4] = { ph[2*ks2][0], ph[2*ks2][1], ph[2*ks2+1][0], ph[2*ks2+1][1] };
            const uint32_t swV = (uint32_t)(((2 * ks2 + gB) ^ l7) << 4);
            #pragma unroll
            for (int p = 0; p < 4; p++) {
                uint32_t v0r, v1r, v2r, v3r;
                LDSM_X4(v0r, v1r, v2r, v3r, vBase + bRow + (uint32_t)(p * 2048) + swV);
                uint32_t bf0[2] = {v0r, v1r}, bf1[2] = {v2r, v3r};
                MMA_F16(oacc[2 * p],     a, bf0);
                MMA_F16(oacc[2 * p + 1], a, bf1);
            }
        }
    }

    // ---- write ctx (fp16): [b][s][h*64+d] ----
    float inv0 = 1.0f / lrow[0], inv1 = 1.0f / lrow[1];
    int h = z & 15;
    __half* crow0 = ctx + ((size_t)b * SEQ + (size_t)(m0 + 16 * w + rq)) * DMODEL + h * DH;
    __half* crow1 = crow0 + (size_t)8 * DMODEL;
    #pragma unroll
    for (int f = 0; f < 8; f++) {
        int d0 = 8 * f + 2 * cc;
        *(uint32_t*)&crow0[d0] = pack_h2(oacc[f][0] * inv0, oacc[f][1] * inv0);
        *(uint32_t*)&crow1[d0] = pack_h2(oacc[f][2] * inv1, oacc[f][3] * inv1);
    }
}

// ================= layernorm ================================================
__device__ __forceinline__ float block_sum(float v, float* sh) {
    #pragma unroll
    for (int o = 16; o; o >>= 1) v += __shfl_xor_sync(0xffffffffu, v, o);
    int lane = threadIdx.x & 31, w = threadIdx.x >> 5;
    __syncthreads();
    if (lane == 0) sh[w] = v;
    __syncthreads();
    if (w == 0) {
        float x = (lane < (blockDim.x >> 5)) ? sh[lane] : 0.0f;
        #pragma unroll
        for (int o = 16; o; o >>= 1) x += __shfl_xor_sync(0xffffffffu, x, o);
        if (lane == 0) sh[0] = x;
    }
    __syncthreads();
    return sh[0];
}
__global__ void ln_k(float* __restrict__ out, const float* __restrict__ gamma,
                     const float* __restrict__ beta) {
    __shared__ float sh[32];
    int row = blockIdx.x, t = threadIdx.x;
    float* p = out + (size_t)row * DMODEL;
    float4 v = *(const float4*)(p + t * 4);
    float mean = block_sum(v.x + v.y + v.z + v.w, sh) * (1.0f / DMODEL);
    float dx = v.x - mean, dy = v.y - mean, dz = v.z - mean, dw = v.w - mean;
    float var = block_sum(dx*dx + dy*dy + dz*dz + dw*dw, sh) * (1.0f / DMODEL);
    float inv = rsqrtf(var + 1e-7f);
    float4 g = *(const float4*)(gamma + t * 4);
    float4 bb = *(const float4*)(beta + t * 4);
    float4 o;
    o.x = dx*inv*g.x + bb.x; o.y = dy*inv*g.y + bb.y;
    o.z = dz*inv*g.z + bb.z; o.w = dw*inv*g.w + bb.w;
    *(float4*)(p + t * 4) = o;
}

// ================= launch ====================================================
extern "C" void kernel_launch(void* const* d_in, const int* in_sizes, int n_in,
                              void* d_out, int out_size) {
    const float* hidden = (const float*)d_in[0];
    const int*   mask   = (const int*)  d_in[1];
    const float* rel    = (const float*)d_in[2];
    const float* Wq     = (const float*)d_in[3];
    const float* bq     = (const float*)d_in[4];
    const float* Wk     = (const float*)d_in[5];
    const float* bk     = (const float*)d_in[6];
    const float* Wv     = (const float*)d_in[7];
    const float* bv     = (const float*)d_in[8];
    const float* Wo     = (const float*)d_in[9];
    const float* bo     = (const float*)d_in[10];
    const float* gamma  = (const float*)d_in[11];
    const float* beta   = (const float*)d_in[12];
    float* out = (float*)d_out;

    __half *hh, *wqkv, *wo, *relh, *qkh, *vt, *pkq, *bias2, *ctx;
    float* bqkv;
    uint32_t* mbits;
    cudaGetSymbolAddress((void**)&hh,    g_hh);
    cudaGetSymbolAddress((void**)&wqkv,  g_wqkv);
    cudaGetSymbolAddress((void**)&bqkv,  g_bqkv);
    cudaGetSymbolAddress((void**)&wo,    g_wo);
    cudaGetSymbolAddress((void**)&relh,  g_relh);
    cudaGetSymbolAddress((void**)&qkh,   g_qkh);
    cudaGetSymbolAddress((void**)&vt,    g_vt);
    cudaGetSymbolAddress((void**)&pkq,   g_pkq);
    cudaGetSymbolAddress((void**)&bias2, g_bias2);
    cudaGetSymbolAddress((void**)&ctx,   g_ctx);
    cudaGetSymbolAddress((void**)&mbits, g_mbits);
    __half* qh   = qkh;
    __half* kh   = qkh + QKOFF;
    __half* c2p  = bias2;
    __half* p2cT = bias2 + BIASOFF;

    const float alpha = LOG2E / sqrtf((float)(DH * 3));
    const size_t SMG = 98304;
    const size_t SMF = 73728;

    cudaFuncSetAttribute((const void*)tc_gemm_h<EPI_QKV,  16>, cudaFuncAttributeMaxDynamicSharedMemorySize, (int)SMG);
    cudaFuncSetAttribute((const void*)tc_gemm_h<EPI_POS,  16>, cudaFuncAttributeMaxDynamicSharedMemorySize, (int)SMG);
    cudaFuncSetAttribute((const void*)tc_gemm_h<EPI_SCALE, 1>, cudaFuncAttributeMaxDynamicSharedMemorySize, (int)SMG);
    cudaFuncSetAttribute((const void*)tc_gemm_h<EPI_OUT,  16>, cudaFuncAttributeMaxDynamicSharedMemorySize, (int)SMG);
    cudaFuncSetAttribute((const void*)flash_k, cudaFuncAttributeMaxDynamicSharedMemorySize, (int)SMF);

    lut_k<<<2, 1024>>>();
    maskpack_k<<<512, 256>>>(mask, mbits);
    bias3_k<<<4, 256>>>(bq, bk, bv, bqkv);
    cvt_k<<<4096, 256>>>(hidden, hh, BDIM * SEQ * DMODEL);
    cvt_k<<<1024, 256>>>(Wq, wqkv,                       DMODEL * DMODEL);
    cvt_k<<<1024, 256>>>(Wk, wqkv + DMODEL * DMODEL,     DMODEL * DMODEL);
    cvt_k<<<1024, 256>>>(Wv, wqkv + 2 * DMODEL * DMODEL, DMODEL * DMODEL);
    cvt_k<<<1024, 256>>>(Wo, wo, DMODEL * DMODEL);
    cvt_k<<<512,  256>>>(rel, relh, TWOSPAN * DMODEL);

    // fused Q/K/V projections: z selects weight/bias/output
    tc_gemm_h<EPI_QKV, 16><<<dim3(8, 32, 3), 256, SMG>>>(
        hh, wqkv, bqkv, 0, (float*)vt, qkh, 1024);
    // merged position projections: z=0 -> pk (Wk), z=1 -> pq (Wq)
    tc_gemm_h<EPI_POS, 16><<<dim3(8, 4, 2), 256, SMG>>>(
        relh, wqkv, bqkv, 0, 0, pkq, 1024);
    // merged SCALE: z<64 -> c2p = qh@pk^T ; z>=64 -> p2cT = pq@kh^T (log2e-scaled)
    tc_gemm_h<EPI_SCALE, 1><<<dim3(32, 1, 128), 256, SMG>>>(
        qkh, pkq, 0, 0, 0, bias2, 64);

    // fused attention (log2-domain softmax)
    flash_k<<<dim3(8, NBATCH), 256, SMF>>>(qh, kh, vt, c2p, p2cT, mbits, ctx, alpha);

    // output projection + residual
    tc_gemm_h<EPI_OUT, 16><<<dim3(8, 32, 1), 256, SMG>>>(ctx, wo, bo, hidden, out, 0, 1024);

    ln_k<<<BDIM * SEQ, 256>>>(out, gamma, beta);
}

// round 16
// speedup vs baseline: 1.0889x; 1.0889x over previous
#include <cuda_runtime.h>
#include <cuda_fp16.h>
#include <math.h>
#include <stdint.h>

#define BDIM 4
#define SEQ 1024
#define DMODEL 1024
#define NH 16
#define DH 64
#define SPAN 256
#define TWOSPAN 512
#define NBATCH (BDIM*NH)   /* 64 */
#define NEGF (-3.402823466e38f)
#define QKOFF ((size_t)NBATCH * SEQ * DH)
#define PKOFF ((size_t)NH * TWOSPAN * DH)
#define BIASOFF ((size_t)NBATCH * SEQ * TWOSPAN)

// ---------------- scratch (device globals; no allocation allowed) ----------
__device__ __half    g_hh   [(size_t)BDIM * SEQ * DMODEL];     // hidden fp16
__device__ __half    g_wqkv [(size_t)3 * DMODEL * DMODEL];     // packed Wq|Wk|Wv fp16
__device__ float     g_bqkv [3 * DMODEL];                       // packed bq|bk|bv
__device__ __half    g_wo   [(size_t)DMODEL * DMODEL];
__device__ __half    g_relh [(size_t)TWOSPAN * DMODEL];
__device__ __half    g_qkh  [(size_t)2 * NBATCH * SEQ * DH];   // qh | kh
__device__ __half    g_vt   [(size_t)NBATCH * DH * SEQ];       // [z][d][s]
__device__ __half    g_pkq  [(size_t)2 * NH * TWOSPAN * DH];   // pk | pq
__device__ __half    g_bias2[(size_t)2 * NBATCH * SEQ * TWOSPAN]; // c2p | p2cT
__device__ __half    g_ctx  [(size_t)BDIM * SEQ * DMODEL];
__device__ uint32_t  g_mbits[(size_t)BDIM * SEQ * 32];          // packed mask bits
__device__ int       g_lut  [2047];

// ================= small helpers ============================================
#define MMA_F16(d, a, b) \
    asm volatile("mma.sync.aligned.m16n8k16.row.col.f32.f16.f16.f32 " \
        "{%0,%1,%2,%3}, {%4,%5,%6,%7}, {%8,%9}, {%0,%1,%2,%3};" \
        : "+f"((d)[0]), "+f"((d)[1]), "+f"((d)[2]), "+f"((d)[3]) \
        : "r"((a)[0]), "r"((a)[1]), "r"((a)[2]), "r"((a)[3]), \
          "r"((b)[0]), "r"((b)[1]))

__device__ __forceinline__ uint32_t pack_h2(float lo, float hi) {
    uint32_t u;
    asm("cvt.rn.f16x2.f32 %0, %1, %2;" : "=r"(u) : "f"(hi), "f"(lo));
    return u;
}
__device__ __forceinline__ void cp16(uint32_t dst, const void* src) {
    asm volatile("cp.async.cg.shared.global [%0], [%1], 16;" :: "r"(dst), "l"(src));
}
#define CP_COMMIT() asm volatile("cp.async.commit_group;" ::: "memory")
#define CP_WAIT(n)  asm volatile("cp.async.wait_group %0;" :: "n"(n) : "memory")

__device__ __forceinline__ int rel_bucket(int rel) {
    float abs_pos = (rel < 128 && rel > -128) ? 127.0f : fabsf((float)rel);
    if (abs_pos <= 128.0f) return rel;
    float sgn = (rel > 0) ? 1.0f : -1.0f;
    float log_pos = ceilf(logf(abs_pos * (1.0f/128.0f)) / logf(511.0f/128.0f) * 127.0f) + 128.0f;
    return (int)(log_pos * sgn);
}

// ================= fused prep kernel (all conversions in one launch) ========
#define CVT_TOT 2228224                 /* float4 units across 6 segments */
__global__ void prep_k(const float* __restrict__ hidden, const float* __restrict__ Wq,
                       const float* __restrict__ Wk, const float* __restrict__ Wv,
                       const float* __restrict__ Wo, const float* __restrict__ rel,
                       const float* __restrict__ bq, const float* __restrict__ bk,
                       const float* __restrict__ bv, const int* __restrict__ mask,
                       __half* __restrict__ hh, __half* __restrict__ wqkv,
                       __half* __restrict__ wo, __half* __restrict__ relh,
                       float* __restrict__ bqkv, uint32_t* __restrict__ mbits)
{
    int gid = blockIdx.x * blockDim.x + threadIdx.x;
    if (gid < CVT_TOT) {
        const float* s; __half* d; int off;
        if (gid < 1048576)      { s = hidden; d = hh;             off = gid; }
        else if (gid < 1310720) { s = Wq;  d = wqkv;              off = gid - 1048576; }
        else if (gid < 1572864) { s = Wk;  d = wqkv + 1048576;    off = gid - 1310720; }
        else if (gid < 1835008) { s = Wv;  d = wqkv + 2097152;    off = gid - 1572864; }
        else if (gid < 2097152) { s = Wo;  d = wo;                off = gid - 1835008; }
        else                    { s = rel; d = relh;              off = gid - 2097152; }
        float4 v = *(const float4*)(s + (size_t)off * 4);
        uint2 o = make_uint2(pack_h2(v.x, v.y), pack_h2(v.z, v.w));
        *(uint2*)(d + (size_t)off * 4) = o;
    } else if (gid < CVT_TOT + 131072) {
        int idx = gid - CVT_TOT;
        const int4* src = (const int4*)(mask + (size_t)idx * 32);
        uint32_t v = 0;
        #pragma unroll
        for (int g = 0; g < 8; g++) {
            int4 x = src[g];
            v |= (x.x ? 1u : 0u) << (4 * g);
            v |= (x.y ? 1u : 0u) << (4 * g + 1);
            v |= (x.z ? 1u : 0u) << (4 * g + 2);
            v |= (x.w ? 1u : 0u) << (4 * g + 3);
        }
        mbits[idx] = v;
    } else if (gid < CVT_TOT + 131072 + 3072) {
        int t = gid - (CVT_TOT + 131072);
        if (t < 1024) bqkv[t] = bq[t];
        else if (t < 2048) bqkv[t] = bk[t - 1024];
        else bqkv[t] = bv[t - 2048];
    } else if (gid < CVT_TOT + 131072 + 3072 + 2047) {
        int t = gid - (CVT_TOT + 131072 + 3072);
        int b = rel_bucket(t - 1023);
        g_lut[t] = min(max(b + SPAN, 0), TWOSPAN - 1);
    }
}
#define PREP_BLOCKS ((CVT_TOT + 131072 + 3072 + 2047 + 255) / 256)

// ================= unified fp16 mma.sync GEMM (C = A @ B^T + epilogues) =====
#define EPI_SCALE   3
#define EPI_OUT     6
#define EPI_QKV     7

template<int EPI, int CH>
__global__ void __launch_bounds__(256, 2)
tc_gemm_h(const __half* __restrict__ A, const __half* __restrict__ A2,
          const __half* __restrict__ Bm,
          const float* __restrict__ bias, const float* __restrict__ ex1,
          float* __restrict__ C, __half* __restrict__ Ch, __half* __restrict__ Ch2,
          int Ka)
{
    constexpr int NS = 3;
    constexpr int TB = 128 * 128;

    extern __shared__ char smc[];
    const uint32_t smemU = (uint32_t)__cvta_generic_to_shared(smc);

    const int tid  = threadIdx.x;
    const int lane = tid & 31, wid = tid >> 5;
    const int wr = wid & 1, wc = wid >> 1;
    const int rq = lane >> 2, cc = lane & 3;
    const int z  = blockIdx.z;

    int m0, n0;
    size_t cbase = 0;
    int ldC = 0;
    int half = 0, zz = 0;
    bool pos = false; int pz = 0;
    if (EPI == EPI_SCALE) {
        half = z >> 6; zz = z & 63;
        int ti = blockIdx.x;
        int mt = half ? (ti & 3) : (ti >> 2);
        int nt = half ? (ti >> 2) : (ti & 3);
        m0 = mt * 128; n0 = nt * 128;
        const __half* qk  = A;     // g_qkh
        const __half* pkq = Bm;    // g_pkq
        if (half) {
            A  = pkq + PKOFF + (size_t)(zz % NH) * TWOSPAN * DH;
            Bm = qk + QKOFF + (size_t)zz * SEQ * DH;
        } else {
            A  = qk + (size_t)zz * SEQ * DH;
            Bm = pkq + (size_t)(zz % NH) * TWOSPAN * DH;
        }
        cbase = ((size_t)half * NBATCH + zz) * ((size_t)SEQ * TWOSPAN);
        ldC = half ? SEQ : TWOSPAN;
        A  += (size_t)m0 * Ka;
        Bm += (size_t)n0 * Ka;
    } else if (EPI == EPI_QKV && z == 3) {
        // merged position projections: whole-CTA early exit keeps syncs safe
        if (blockIdx.y >= 8) return;
        pos = true;
        pz = blockIdx.y >> 2;                 // 0 -> pk (Wk), 1 -> pq (Wq)
        m0 = (blockIdx.y & 3) * 128;
        n0 = blockIdx.x * 128;
        A  = A2 + (size_t)m0 * Ka;            // relh
        Bm += (size_t)(1 - pz) * DMODEL * DMODEL + (size_t)n0 * Ka;
    } else {
        m0 = blockIdx.y * 128;
        n0 = blockIdx.x * 128;
        if (EPI == EPI_QKV) {
            Bm += (size_t)z * DMODEL * DMODEL;
        }
        A  += (size_t)m0 * Ka;
        Bm += (size_t)n0 * Ka;
    }

    float acc[4][4][4];
    #pragma unroll
    for (int a = 0; a < 4; a++)
        #pragma unroll
        for (int b = 0; b < 4; b++)
            #pragma unroll
            for (int c = 0; c < 4; c++) acc[a][b][c] = 0.0f;

    const int crow = tid >> 3;
    const int cg   = tid & 7;

    auto issue = [&](int chunk) {
        const int s  = chunk % NS;
        const int k0 = chunk * 64;
        #pragma unroll
        for (int j = 0; j < 4; j++) {
            int row = j * 32 + crow;
            cp16(smemU + (uint32_t)(s * TB + row * 128 + ((cg ^ (row & 7)) << 4)),
                 A + (size_t)row * Ka + k0 + cg * 8);
        }
        #pragma unroll
        for (int j = 0; j < 4; j++) {
            int row = j * 32 + crow;
            cp16(smemU + (uint32_t)(NS * TB + s * TB + row * 128 + ((cg ^ (row & 7)) << 4)),
                 Bm + (size_t)row * Ka + k0 + cg * 8);
        }
    };

    #pragma unroll
    for (int c = 0; c < NS - 1; c++) {
        if (c < CH) issue(c);
        CP_COMMIT();
    }

    #pragma unroll 1
    for (int i = 0; i < CH; i++) {
        CP_WAIT(NS - 2);
        __syncthreads();
        if (i + NS - 1 < CH) issue(i + NS - 1);
        CP_COMMIT();

        const char* as = smc + (i % NS) * TB;
        const char* bs = smc + NS * TB + (i % NS) * TB;
        #pragma unroll
        for (int kc = 0; kc < 4; kc++) {
            const int o0 = (((2 * kc)     ^ rq) << 4) + 4 * cc;
            const int o1 = (((2 * kc + 1) ^ rq) << 4) + 4 * cc;
            uint32_t af[4][4];
            #pragma unroll
            for (int mi = 0; mi < 4; mi++) {
                int rA = wr * 64 + mi * 16 + rq;
                af[mi][0] = *(const uint32_t*)(as + rA * 128 + o0);
                af[mi][1] = *(const uint32_t*)(as + (rA + 8) * 128 + o0);
                af[mi][2] = *(const uint32_t*)(as + rA * 128 + o1);
                af[mi][3] = *(const uint32_t*)(as + (rA + 8) * 128 + o1);
            }
            uint32_t bf[4][2];
            #pragma unroll
            for (int ni = 0; ni < 4; ni++) {
                int rn = wc * 32 + ni * 8 + rq;
                bf[ni][0] = *(const uint32_t*)(bs + rn * 128 + o0);
                bf[ni][1] = *(const uint32_t*)(bs + rn * 128 + o1);
            }
            #pragma unroll
            for (int mi = 0; mi < 4; mi++)
                #pragma unroll
                for (int ni = 0; ni < 4; ni++)
                    MMA_F16(acc[mi][ni], af[mi], bf[ni]);
        }
    }
    CP_WAIT(0);
    __syncthreads();

    // ---------------- epilogue: frags -> smem stage -> global ----------------
    float* stage = (float*)smc;
    const int boff = (EPI == EPI_QKV) ? (pos ? (1 - pz) * DMODEL : z * DMODEL) : 0;
    const bool transT = (EPI == EPI_QKV && z == 2);
    const float alpha = 0.072168783648703216f;   // 1/sqrt(192)

    #pragma unroll 1
    for (int cb = 0; cb < 4; cb++) {
        const int n0c = n0 + cb * 32;
        #pragma unroll
        for (int mi = 0; mi < 4; mi++)
            #pragma unroll
            for (int ni = 0; ni < 4; ni++) {
                int gc = wc * 32 + ni * 8 + 2 * cc;
                if ((gc >> 5) == cb) {
                    int sc2 = gc & 31;
                    int r0 = wr * 64 + mi * 16 + rq;
                    stage[r0 * 33 + sc2]           = acc[mi][ni][0];
                    stage[r0 * 33 + sc2 + 1]       = acc[mi][ni][1];
                    stage[(r0 + 8) * 33 + sc2]     = acc[mi][ni][2];
                    stage[(r0 + 8) * 33 + sc2 + 1] = acc[mi][ni][3];
                }
            }
        __syncthreads();

        if (transT) {
            __half* Vp = (__half*)C;
            #pragma unroll 1
            for (int j = 0; j < 16; j++) {
                int e = j * 256 + tid;
                int row = e & 127, c = e >> 7;
                int m = m0 + row, n = n0c + c;
                float val = stage[row * 33 + c] + bias[boff + n];
                int b = m >> 10, sq = m & 1023;
                int zidx = b * NH + (n >> 6), dd = n & 63;
                Vp[((size_t)zidx * DH + dd) * SEQ + sq] = __float2half(val);
            }
        } else {
            #pragma unroll 1
            for (int j = 0; j < 16; j++) {
                int e = j * 256 + tid;
                int row = e >> 5, c = e & 31;
                int m = m0 + row, n = n0c + c;
                float val = stage[row * 33 + c];
                if (EPI == EPI_QKV) {
                    val += bias[boff + n];
                    int h = n >> 6, dd = n & 63;
                    if (pos) {
                        Ch2[(size_t)pz * PKOFF + ((size_t)h * TWOSPAN + m) * DH + dd] = __float2half(val);
                    } else {
                        int b = m >> 10, sq = m & 1023;
                        size_t idx = (((size_t)(b * NH + h)) * SEQ + sq) * DH + dd;
                        Ch[(size_t)z * QKOFF + idx] = __float2half(val);
                    }
                } else if (EPI == EPI_SCALE) {
                    Ch[cbase + (size_t)m * ldC + n] = __float2half(val * alpha);
                } else { // EPI_OUT
                    val += bias[n] + ex1[(size_t)m * DMODEL + n];
                    C[(size_t)m * DMODEL + n] = val;
                }
            }
        }
        __syncthreads();
    }
}

// ================= flash attention (all-fp16 MMA, 3-stage KV, bitmask) ======
// grid (8 q-tiles, 64 z), 256 threads = 8 warps; warp w owns q rows 16w..16w+15.
// smem bytes: Q 16K | K 3x8K | V 3x8K | lut 8K => 72KB, 2 CTA/SM
__global__ void __launch_bounds__(256, 2)
flash_k(const __half* __restrict__ Qg, const __half* __restrict__ Kg,
        const __half* __restrict__ Vg, const __half* __restrict__ c2p,
        const __half* __restrict__ p2cT, const uint32_t* __restrict__ mbits,
        __half* __restrict__ ctx, float alpha)
{
    constexpr int QSB = 0, KSB = 16384, VSB = 40960, LUTB = 65536;
    extern __shared__ float fsm[];
    char* smc = (char*)fsm;
    int* lut_s = (int*)(smc + LUTB);
    const uint32_t smemU = (uint32_t)__cvta_generic_to_shared(fsm);

    const int tid = threadIdx.x, lane = tid & 31, w = tid >> 5;
    const int rq = lane >> 2, cc = lane & 3;
    const int z = blockIdx.y, m0 = blockIdx.x * 128;
    const int b = z >> 4;

    const __half* Qz = Qg + (size_t)z * SEQ * DH;
    const __half* Kz = Kg + (size_t)z * SEQ * DH;
    const __half* Vz = Vg + (size_t)z * DH * SEQ;
    const __half* c2pz = c2p + (size_t)z * SEQ * TWOSPAN;
    const __half* p2cz = p2cT + (size_t)z * TWOSPAN * SEQ;

    for (int t = tid; t < 2047; t += 256) lut_s[t] = g_lut[t];

    #pragma unroll
    for (int it = 0; it < 4; it++) {
        int idx = it * 256 + tid;
        int row = idx >> 3, g = idx & 7;
        cp16(smemU + (uint32_t)(QSB + row * 128 + ((g ^ (row & 7)) << 4)),
             Qz + (size_t)(m0 + row) * DH + g * 8);
    }
    auto issueKV = [&](int t) {
        int s = t % 3, n0 = t * 64;
        #pragma unroll
        for (int it = 0; it < 2; it++) {
            int idx = it * 256 + tid;
            int row = idx >> 3, g = idx & 7;
            cp16(smemU + (uint32_t)(KSB + s * 8192 + row * 128 + ((g ^ (row & 7)) << 4)),
                 Kz + (size_t)(n0 + row) * DH + g * 8);
        }
        #pragma unroll
        for (int it = 0; it < 2; it++) {
            int idx = it * 256 + tid;
            int row = idx >> 3, g = idx & 7;
            cp16(smemU + (uint32_t)(VSB + s * 8192 + row * 128 + ((g ^ (row & 7)) << 4)),
                 Vz + (size_t)row * SEQ + n0 + g * 8);
        }
    };
    issueKV(0);
    CP_COMMIT();
    issueKV(1);
    CP_COMMIT();

    float oacc[8][4];
    #pragma unroll
    for (int f = 0; f < 8; f++)
        #pragma unroll
        for (int e = 0; e < 4; e++) oacc[f][e] = 0.0f;
    float mrow[2] = {NEGF, NEGF};
    float lrow[2] = {0.0f, 0.0f};

    const int iA = m0 + 16 * w + rq, iB = iA + 8;
    const __half* c2pA = c2pz + (size_t)iA * TWOSPAN;
    const __half* c2pB = c2pz + (size_t)iB * TWOSPAN;
    const uint32_t* bmA = mbits + ((size_t)b * SEQ + iA) * 32;
    const uint32_t* bmB = mbits + ((size_t)b * SEQ + iB) * 32;
    const int rowA = 16 * w + rq, rowB = rowA + 8;

    #pragma unroll 1
    for (int t = 0; t < 16; t++) {
        const int s = t % 3, n0 = t * 64;
        CP_WAIT(1);
        __syncthreads();
        if (t + 2 < 16) issueKV(t + 2);
        CP_COMMIT();

        // ---- S = Q @ K^T (fp16 m16n8k16, 4 k-chunks) ----
        float sacc[8][4];
        #pragma unroll
        for (int f = 0; f < 8; f++)
            #pragma unroll
            for (int e = 0; e < 4; e++) sacc[f][e] = 0.0f;
        const char* kp = smc + KSB + s * 8192;
        #pragma unroll
        for (int kc = 0; kc < 4; kc++) {
            int g0 = 2 * kc, g1 = 2 * kc + 1;
            uint32_t a[4];
            a[0] = *(const uint32_t*)(smc + QSB + rowA * 128 + ((g0 ^ (rowA & 7)) << 4) + 4 * cc);
            a[1] = *(const uint32_t*)(smc + QSB + rowB * 128 + ((g0 ^ (rowB & 7)) << 4) + 4 * cc);
            a[2] = *(const uint32_t*)(smc + QSB + rowA * 128 + ((g1 ^ (rowA & 7)) << 4) + 4 * cc);
            a[3] = *(const uint32_t*)(smc + QSB + rowB * 128 + ((g1 ^ (rowB & 7)) << 4) + 4 * cc);
            #pragma unroll
            for (int f = 0; f < 8; f++) {
                int rk = 8 * f + rq;
                uint32_t bf[2];
                bf[0] = *(const uint32_t*)(kp + rk * 128 + ((g0 ^ (rk & 7)) << 4) + 4 * cc);
                bf[1] = *(const uint32_t*)(kp + rk * 128 + ((g1 ^ (rk & 7)) << 4) + 4 * cc);
                MMA_F16(sacc[f], a, bf);
            }
        }

        // ---- mask bits for this 64-wide tile ----
        uint2 wA2 = *(const uint2*)&bmA[n0 >> 5];
        uint2 wB2 = *(const uint2*)&bmB[n0 >> 5];
        uint64_t mwA = (uint64_t)wA2.x | ((uint64_t)wA2.y << 32);
        uint64_t mwB = (uint64_t)wB2.x | ((uint64_t)wB2.y << 32);

        // ---- scale + c2p + p2c + mask, row max ----
        float mx0 = NEGF, mx1 = NEGF;
        #pragma unroll
        for (int f = 0; f < 8; f++) {
            int jl = 8 * f + 2 * cc;
            int j0 = n0 + jl;
            bool ma0 = (mwA >> jl) & 1, ma1 = (mwA >> (jl + 1)) & 1;
            bool mb0 = (mwB >> jl) & 1, mb1 = (mwB >> (jl + 1)) & 1;
            float v0 = ma0 ? sacc[f][0] * alpha + __half2float(c2pA[lut_s[iA - j0 + 1023]])
                             + __half2float(p2cz[(size_t)lut_s[j0 - iA + 1023] * SEQ + j0]) : NEGF;
            float v1 = ma1 ? sacc[f][1] * alpha + __half2float(c2pA[lut_s[iA - j0 + 1022]])
                             + __half2float(p2cz[(size_t)lut_s[j0 + 1 - iA + 1023] * SEQ + j0 + 1]) : NEGF;
            float v2 = mb0 ? sacc[f][2] * alpha + __half2float(c2pB[lut_s[iB - j0 + 1023]])
                             + __half2float(p2cz[(size_t)lut_s[j0 - iB + 1023] * SEQ + j0]) : NEGF;
            float v3 = mb1 ? sacc[f][3] * alpha + __half2float(c2pB[lut_s[iB - j0 + 1022]])
                             + __half2float(p2cz[(size_t)lut_s[j0 + 1 - iB + 1023] * SEQ + j0 + 1]) : NEGF;
            sacc[f][0] = v0; sacc[f][1] = v1; sacc[f][2] = v2; sacc[f][3] = v3;
            mx0 = fmaxf(mx0, fmaxf(v0, v1));
            mx1 = fmaxf(mx1, fmaxf(v2, v3));
        }
        mx0 = fmaxf(mx0, __shfl_xor_sync(0xffffffffu, mx0, 1));
        mx0 = fmaxf(mx0, __shfl_xor_sync(0xffffffffu, mx0, 2));
        mx1 = fmaxf(mx1, __shfl_xor_sync(0xffffffffu, mx1, 1));
        mx1 = fmaxf(mx1, __shfl_xor_sync(0xffffffffu, mx1, 2));
        float mn0 = fmaxf(mrow[0], mx0), mn1 = fmaxf(mrow[1], mx1);
        float sc0 = __expf(mrow[0] - mn0), sc1 = __expf(mrow[1] - mn1);
        mrow[0] = mn0; mrow[1] = mn1;

        // ---- exp, pack P to fp16 A-fragments in-register ----
        float rs0 = 0.0f, rs1 = 0.0f;
        uint32_t ph[8][2];
        #pragma unroll
        for (int f = 0; f < 8; f++) {
            float e0 = __expf(sacc[f][0] - mn0);
            float e1 = __expf(sacc[f][1] - mn0);
            float e2 = __expf(sacc[f][2] - mn1);
            float e3 = __expf(sacc[f][3] - mn1);
            rs0 += e0 + e1; rs1 += e2 + e3;
            float p0 = (sacc[f][0] == NEGF) ? 0.0f : e0;
            float p1 = (sacc[f][1] == NEGF) ? 0.0f : e1;
            float p2 = (sacc[f][2] == NEGF) ? 0.0f : e2;
            float p3 = (sacc[f][3] == NEGF) ? 0.0f : e3;
            ph[f][0] = pack_h2(p0, p1);
            ph[f][1] = pack_h2(p2, p3);
        }
        rs0 += __shfl_xor_sync(0xffffffffu, rs0, 1);
        rs0 += __shfl_xor_sync(0xffffffffu, rs0, 2);
        rs1 += __shfl_xor_sync(0xffffffffu, rs1, 1);
        rs1 += __shfl_xor_sync(0xffffffffu, rs1, 2);
        lrow[0] = lrow[0] * sc0 + rs0;
        lrow[1] = lrow[1] * sc1 + rs1;
        #pragma unroll
        for (int f = 0; f < 8; f++) {
            oacc[f][0] *= sc0; oacc[f][1] *= sc0;
            oacc[f][2] *= sc1; oacc[f][3] *= sc1;
        }

        // ---- O += P @ V (fp16, P in registers, V fp16 smem) ----
        const char* vp = smc + VSB + s * 8192;
        #pragma unroll
        for (int ks2 = 0; ks2 < 4; ks2++) {
            uint32_t a[4] = { ph[2*ks2][0], ph[2*ks2][1], ph[2*ks2+1][0], ph[2*ks2+1][1] };
            int g0 = (2 * ks2) ^ rq, g1 = (2 * ks2 + 1) ^ rq;
            #pragma unroll
            for (int n = 0; n < 8; n++) {
                int d = 8 * n + rq;
                uint32_t bf[2];
                bf[0] = *(const uint32_t*)(vp + d * 128 + (g0 << 4) + 4 * cc);
                bf[1] = *(const uint32_t*)(vp + d * 128 + (g1 << 4) + 4 * cc);
                MMA_F16(oacc[n], a, bf);
            }
        }
    }

    // ---- write ctx (fp16): [b][s][h*64+d] ----
    float inv0 = 1.0f / lrow[0], inv1 = 1.0f / lrow[1];
    int h = z & 15;
    __half* crow0 = ctx + ((size_t)b * SEQ + (size_t)(m0 + 16 * w + rq)) * DMODEL + h * DH;
    __half* crow1 = crow0 + (size_t)8 * DMODEL;
    #pragma unroll
    for (int f = 0; f < 8; f++) {
        int d0 = 8 * f + 2 * cc;
        *(uint32_t*)&crow0[d0] = pack_h2(oacc[f][0] * inv0, oacc[f][1] * inv0);
        *(uint32_t*)&crow1[d0] = pack_h2(oacc[f][2] * inv1, oacc[f][3] * inv1);
    }
}

// ================= layernorm ================================================
__device__ __forceinline__ float block_sum(float v, float* sh) {
    #pragma unroll
    for (int o = 16; o; o >>= 1) v += __shfl_xor_sync(0xffffffffu, v, o);
    int lane = threadIdx.x & 31, w = threadIdx.x >> 5;
    __syncthreads();
    if (lane == 0) sh[w] = v;
    __syncthreads();
    if (w == 0) {
        float x = (lane < (blockDim.x >> 5)) ? sh[lane] : 0.0f;
        #pragma unroll
        for (int o = 16; o; o >>= 1) x += __shfl_xor_sync(0xffffffffu, x, o);
        if (lane == 0) sh[0] = x;
    }
    __syncthreads();
    return sh[0];
}
__global__ void ln_k(float* __restrict__ out, const float* __restrict__ gamma,
                     const float* __restrict__ beta) {
    __shared__ float sh[32];
    int row = blockIdx.x, t = threadIdx.x;
    float* p = out + (size_t)row * DMODEL;
    float4 v = *(const float4*)(p + t * 4);
    float mean = block_sum(v.x + v.y + v.z + v.w, sh) * (1.0f / DMODEL);
    float dx = v.x - mean, dy = v.y - mean, dz = v.z - mean, dw = v.w - mean;
    float var = block_sum(dx*dx + dy*dy + dz*dz + dw*dw, sh) * (1.0f / DMODEL);
    float inv = rsqrtf(var + 1e-7f);
    float4 g = *(const float4*)(gamma + t * 4);
    float4 bb = *(const float4*)(beta + t * 4);
    float4 o;
    o.x = dx*inv*g.x + bb.x; o.y = dy*inv*g.y + bb.y;
    o.z = dz*inv*g.z + bb.z; o.w = dw*inv*g.w + bb.w;
    *(float4*)(p + t * 4) = o;
}

// ================= launch ====================================================
extern "C" void kernel_launch(void* const* d_in, const int* in_sizes, int n_in,
                              void* d_out, int out_size) {
    const float* hidden = (const float*)d_in[0];
    const int*   mask   = (const int*)  d_in[1];
    const float* rel    = (const float*)d_in[2];
    const float* Wq     = (const float*)d_in[3];
    const float* bq     = (const float*)d_in[4];
    const float* Wk     = (const float*)d_in[5];
    const float* bk     = (const float*)d_in[6];
    const float* Wv     = (const float*)d_in[7];
    const float* bv     = (const float*)d_in[8];
    const float* Wo     = (const float*)d_in[9];
    const float* bo     = (const float*)d_in[10];
    const float* gamma  = (const float*)d_in[11];
    const float* beta   = (const float*)d_in[12];
    float* out = (float*)d_out;

    __half *hh, *wqkv, *wo, *relh, *qkh, *vt, *pkq, *bias2, *ctx;
    float* bqkv;
    uint32_t* mbits;
    cudaGetSymbolAddress((void**)&hh,    g_hh);
    cudaGetSymbolAddress((void**)&wqkv,  g_wqkv);
    cudaGetSymbolAddress((void**)&bqkv,  g_bqkv);
    cudaGetSymbolAddress((void**)&wo,    g_wo);
    cudaGetSymbolAddress((void**)&relh,  g_relh);
    cudaGetSymbolAddress((void**)&qkh,   g_qkh);
    cudaGetSymbolAddress((void**)&vt,    g_vt);
    cudaGetSymbolAddress((void**)&pkq,   g_pkq);
    cudaGetSymbolAddress((void**)&bias2, g_bias2);
    cudaGetSymbolAddress((void**)&ctx,   g_ctx);
    cudaGetSymbolAddress((void**)&mbits, g_mbits);
    __half* qh   = qkh;
    __half* kh   = qkh + QKOFF;
    __half* c2p  = bias2;
    __half* p2cT = bias2 + BIASOFF;

    const float alpha = 1.0f / sqrtf((float)(DH * 3));
    const size_t SMG = 98304;
    const size_t SMF = 73728;

    cudaFuncSetAttribute((const void*)tc_gemm_h<EPI_QKV,  16>, cudaFuncAttributeMaxDynamicSharedMemorySize, (int)SMG);
    cudaFuncSetAttribute((const void*)tc_gemm_h<EPI_SCALE, 1>, cudaFuncAttributeMaxDynamicSharedMemorySize, (int)SMG);
    cudaFuncSetAttribute((const void*)tc_gemm_h<EPI_OUT,  16>, cudaFuncAttributeMaxDynamicSharedMemorySize, (int)SMG);
    cudaFuncSetAttribute((const void*)flash_k, cudaFuncAttributeMaxDynamicSharedMemorySize, (int)SMF);

    // single fused prep launch: all fp16 conversions + mask pack + biases + lut
    prep_k<<<PREP_BLOCKS, 256>>>(hidden, Wq, Wk, Wv, Wo, rel, bq, bk, bv, mask,
                                 hh, wqkv, wo, relh, bqkv, mbits);

    // fused Q/K/V + position projections: z in {0,1,2}=QKV, z=3 (y<8)=pos
    tc_gemm_h<EPI_QKV, 16><<<dim3(8, 32, 4), 256, SMG>>>(
        hh, relh, wqkv, bqkv, 0, (float*)vt, qkh, pkq, 1024);
    // merged SCALE: z<64 -> c2p = qh@pk^T ; z>=64 -> p2cT = pq@kh^T
    tc_gemm_h<EPI_SCALE, 1><<<dim3(32, 1, 128), 256, SMG>>>(
        qkh, 0, pkq, 0, 0, 0, bias2, 0, 64);

    // fused attention
    flash_k<<<dim3(8, NBATCH), 256, SMF>>>(qh, kh, vt, c2p, p2cT, mbits, ctx, alpha);

    // output projection + residual
    tc_gemm_h<EPI_OUT, 16><<<dim3(8, 32, 1), 256, SMG>>>(
        ctx, 0, wo, bo, hidden, out, 0, 0, 1024);

    ln_k<<<BDIM * SEQ, 256>>>(out, gamma, beta);
}